// round 17
// baseline (speedup 1.0000x reference)
#include <cuda_runtime.h>
#include <cuda_fp16.h>
#include <cstdint>

namespace {

constexpr int ROWS = 32;           // edges per CTA
constexpr int THREADS = 128;       // 4 warps
constexpr int BLKW = 132;          // uint32 words per A frag block (512B data + 16B pad)
constexpr int KBA = 24;            // kb blocks per mb in A region (16 for x/h + 8 winding)
constexpr int P_OFF = 2 * KBA * BLKW;   // 6336
constexpr int BSM_OFF = P_OFF + 2240;
constexpr int SQ_OFF = BSM_OFF + 32;    // LN partials: 32 rows x 8 floats
constexpr int SMF = SQ_OFF + 256;
constexpr int SMEM_BYTES = SMF * 4;     // 35456 B -> 4 CTAs/SM (reg-limited)

constexpr int Pb1 = 0, Pg1 = 256, Pt1 = 512, Pb2 = 768, Pg2 = 1024, Pt2 = 1280;
constexpr int Pb3 = 1536, PWw = 1600, Pbw = 1856, Pgw = 1984, Ptw = 2112;

// fp16 weights packed for LDG.128: per kb16-row, [gg][pair][lane][4 uints]
// W1: 24 kb x 2048, W2: 16 x 2048, W3: 16 x 512
constexpr int W2B = 49152, W3B = 81920;
__device__ uint32_t g_wt[90112];
__device__ int g_is64;

__device__ __forceinline__ uint32_t h2u(__half2 h) { return *reinterpret_cast<uint32_t*>(&h); }

__device__ __forceinline__ void mma16(float* d, const uint32_t* a, uint32_t b0, uint32_t b1) {
    asm volatile(
        "mma.sync.aligned.m16n8k16.row.col.f32.f16.f16.f32 "
        "{%0,%1,%2,%3},{%4,%5,%6,%7},{%8,%9},{%0,%1,%2,%3};\n"
        : "+f"(d[0]), "+f"(d[1]), "+f"(d[2]), "+f"(d[3])
        : "r"(a[0]), "r"(a[1]), "r"(a[2]), "r"(a[3]), "r"(b0), "r"(b1));
}
__device__ __forceinline__ int a_word(int mb, int kb) { return (mb * KBA + kb) * BLKW; }

// B mainloop: PAIRS x LDG.128, fully coalesced
template <int NT>
__device__ __forceinline__ void ldB(const uint32_t* __restrict__ Wb, int kb, int nbstride,
                                    int gg, int lane, uint2 (&br)[NT]) {
    constexpr int PAIRS = NT / 2;
    const uint32_t* base = Wb + (size_t)kb * nbstride + gg * (PAIRS * 128) + lane * 4;
#pragma unroll
    for (int p = 0; p < PAIRS; p++) {
        uint4 q = *(const uint4*)(base + p * 128);
        br[2 * p]     = make_uint2(q.x, q.y);
        br[2 * p + 1] = make_uint2(q.z, q.w);
    }
}
template <int MT>
__device__ __forceinline__ void ldA(const uint32_t* __restrict__ As, int mb0, int kb,
                                    int lane, uint32_t (&a)[MT][4]) {
#pragma unroll
    for (int mt = 0; mt < MT; mt++) {
        uint4 av = *(const uint4*)(As + a_word(mb0 + mt, kb) + lane * 4);
        a[mt][0] = av.x; a[mt][1] = av.y; a[mt][2] = av.z; a[mt][3] = av.w;
    }
}
template <int MT, int NT>
__device__ __forceinline__ void kstep(const uint32_t (&a)[MT][4], const uint2 (&br)[NT],
                                      float (&acc)[MT][NT][4]) {
#pragma unroll
    for (int nt = 0; nt < NT; nt++)
#pragma unroll
        for (int mt = 0; mt < MT; mt++) mma16(acc[mt][nt], a[mt], br[nt].x, br[nt].y);
}

// Barrier-free GEMM, both operands pipelined one kstep ahead.
// KB compile-time: fully unrolled, no dummy tail prefetches.
template <int KB, int MT, int NT>
__device__ __forceinline__ void gemm_ldg(
    const uint32_t* __restrict__ Wb, const int nbstride,
    const uint32_t* __restrict__ As, float (&acc)[MT][NT][4],
    const int mb0, const int gg, const int lane)
{
    uint2 b0[NT], b1[NT];
    uint32_t a0[MT][4], a1[MT][4];
    ldB<NT>(Wb, 0, nbstride, gg, lane, b0);
    ldA<MT>(As, mb0, 0, lane, a0);
#pragma unroll
    for (int kb = 0; kb < KB; kb += 2) {
        ldB<NT>(Wb, kb + 1, nbstride, gg, lane, b1);
        ldA<MT>(As, mb0, kb + 1, lane, a1);
        kstep<MT, NT>(a0, b0, acc);
        if (kb + 2 < KB) {
            ldB<NT>(Wb, kb + 2, nbstride, gg, lane, b0);
            ldA<MT>(As, mb0, kb + 2, lane, a0);
        }
        kstep<MT, NT>(a1, b1, acc);
    }
}

// Fused epilogue: bias + LayerNorm + ReLU + fp16 store (STS.64), single A write pass.
__device__ __forceinline__ void epilogue_ln(
    uint32_t* __restrict__ A, float* __restrict__ SQ, float (&acc)[2][8][4],
    const float* __restrict__ bias, const float* __restrict__ g,
    const float* __restrict__ bt, int nb0, int lane)
{
    const int gid = lane >> 2, tig = lane & 3;
    float s[2][2] = {{0.f,0.f},{0.f,0.f}}, q[2][2] = {{0.f,0.f},{0.f,0.f}};
#pragma unroll
    for (int mt = 0; mt < 2; mt++)
#pragma unroll
        for (int nt = 0; nt < 8; nt++) {
            int c0 = (nb0 + nt) * 8 + 2 * tig;
            float b0v = bias[c0], b1v = bias[c0 + 1];
            acc[mt][nt][0] += b0v; acc[mt][nt][1] += b1v;
            acc[mt][nt][2] += b0v; acc[mt][nt][3] += b1v;
            s[mt][0] += acc[mt][nt][0] + acc[mt][nt][1];
            s[mt][1] += acc[mt][nt][2] + acc[mt][nt][3];
            q[mt][0] += acc[mt][nt][0] * acc[mt][nt][0] + acc[mt][nt][1] * acc[mt][nt][1];
            q[mt][1] += acc[mt][nt][2] * acc[mt][nt][2] + acc[mt][nt][3] * acc[mt][nt][3];
        }
#pragma unroll
    for (int mt = 0; mt < 2; mt++)
#pragma unroll
        for (int h = 0; h < 2; h++) {
            s[mt][h] += __shfl_xor_sync(~0u, s[mt][h], 1);
            s[mt][h] += __shfl_xor_sync(~0u, s[mt][h], 2);
            q[mt][h] += __shfl_xor_sync(~0u, q[mt][h], 1);
            q[mt][h] += __shfl_xor_sync(~0u, q[mt][h], 2);
        }
    const int cg = nb0 >> 3;
    if (tig == 0) {
#pragma unroll
        for (int mt = 0; mt < 2; mt++)
#pragma unroll
            for (int h = 0; h < 2; h++) {
                int r = mt * 16 + gid + h * 8;
                SQ[r * 8 + cg * 2]     = s[mt][h];
                SQ[r * 8 + cg * 2 + 1] = q[mt][h];
            }
    }
    __syncthreads();   // partials visible; also: all warps finished GEMM A-reads
    float mu[2][2], rs[2][2];
#pragma unroll
    for (int mt = 0; mt < 2; mt++)
#pragma unroll
        for (int h = 0; h < 2; h++) {
            int r = mt * 16 + gid + h * 8;
            float4 v0 = *(const float4*)(SQ + r * 8);
            float4 v1 = *(const float4*)(SQ + r * 8 + 4);
            float S = v0.x + v0.z + v1.x + v1.z;
            float Q = v0.y + v0.w + v1.y + v1.w;
            float m = S * (1.f / 256.f);
            mu[mt][h] = m;
            rs[mt][h] = rsqrtf(fmaf(-m, m, Q * (1.f / 256.f)) + 1e-5f);
        }
#pragma unroll
    for (int mt = 0; mt < 2; mt++)
#pragma unroll
        for (int nt = 0; nt < 8; nt++) {
            int c0 = (nb0 + nt) * 8 + 2 * tig;
            float2 gv = *(const float2*)(g + c0);
            float2 bv = *(const float2*)(bt + c0);
            int kb = c0 >> 4, hic = (c0 >> 3) & 1;
            int idx = a_word(mt, kb) + lane * 4 + 2 * hic;
            float y0 = fmaxf(fmaf((acc[mt][nt][0] - mu[mt][0]) * rs[mt][0], gv.x, bv.x), 0.f);
            float y1 = fmaxf(fmaf((acc[mt][nt][1] - mu[mt][0]) * rs[mt][0], gv.y, bv.y), 0.f);
            float y2 = fmaxf(fmaf((acc[mt][nt][2] - mu[mt][1]) * rs[mt][1], gv.x, bv.x), 0.f);
            float y3 = fmaxf(fmaf((acc[mt][nt][3] - mu[mt][1]) * rs[mt][1], gv.y, bv.y), 0.f);
            uint2 w2 = make_uint2(h2u(__floats2half2_rn(y0, y1)),
                                  h2u(__floats2half2_rn(y2, y3)));
            *(uint2*)(A + idx) = w2;
        }
}

}  // namespace

// pack fp16 weights for coalesced LDG.128; also detect batch dtype
__global__ void prep_weights(const float* __restrict__ W1, const float* __restrict__ W2,
                             const float* __restrict__ W3, const int* __restrict__ b32) {
    if (blockIdx.x == 0 && threadIdx.x < 32) {
        int bad = (b32[2 * threadIdx.x + 1] != 0);
        unsigned m = __ballot_sync(~0u, bad);
        if (threadIdx.x == 0) g_is64 = (m == 0);
    }
    int id = blockIdx.x * 256 + threadIdx.x;
    if (id >= 90112) return;
    const float* W; int t, ncols, rowsz;
    if (id < W2B)      { W = W1; t = id;       ncols = 256; rowsz = 2048; }
    else if (id < W3B) { W = W2; t = id - W2B; ncols = 256; rowsz = 2048; }
    else               { W = W3; t = id - W3B; ncols = 64;  rowsz = 512;  }
    int kb = t / rowsz, rem = t % rowsz;
    int nb, reg, lane;
    if (rowsz == 2048) {          // NT=8 pack: [gg][p][lane][4]
        int gg = rem >> 9, rr = rem & 511;
        int p = rr >> 7, rr2 = rr & 127;
        lane = rr2 >> 2;
        int j = rr2 & 3;
        nb = gg * 8 + 2 * p + (j >> 1);
        reg = j & 1;
    } else {                      // W3 pack: [gg][lane][4], gg holds nb pair
        int gg = rem >> 7, rr2 = rem & 127;
        lane = rr2 >> 2;
        int j = rr2 & 3;
        nb = gg * 2 + (j >> 1);
        reg = j & 1;
    }
    int gid = lane >> 2, tig = lane & 3;
    int k = kb * 16 + tig * 2 + reg * 8;
    int n = nb * 8 + gid;
    __half2 h = __floats2half2_rn(W[k * ncols + n], W[(k + 1) * ncols + n]);
    g_wt[id] = *reinterpret_cast<uint32_t*>(&h);
}

__global__ void __launch_bounds__(THREADS, 4)
fused_edge_kernel(const float* __restrict__ src, const float* __restrict__ dst_,
                  const float* __restrict__ ea, const float* __restrict__ u,
                  const void* __restrict__ braw, const float* __restrict__ wind,
                  const float* __restrict__ bw, const float* __restrict__ gw,
                  const float* __restrict__ btw, const float* __restrict__ Ww,
                  const float* __restrict__ b1, const float* __restrict__ g1,
                  const float* __restrict__ bt1, const float* __restrict__ b2,
                  const float* __restrict__ g2, const float* __restrict__ bt2,
                  const float* __restrict__ b3, float* __restrict__ out, int E)
{
    extern __shared__ float sm[];
    uint32_t* As = (uint32_t*)sm;
    float* P  = sm + P_OFF;
    int* bsm  = (int*)(sm + BSM_OFF);
    float* SQ = sm + SQ_OFF;

    const int tid = threadIdx.x;
    const int warp = tid >> 5, lane = tid & 31;
    const int gid = lane >> 2, tig = lane & 3;
    const int e0 = blockIdx.x * ROWS;
    const int is64 = g_is64;

    // params + batch ids (128 threads)
#pragma unroll
    for (int t = tid; t < 256; t += THREADS) {
        P[PWw + t] = Ww[t];
        P[Pb1 + t] = b1[t]; P[Pg1 + t] = g1[t]; P[Pt1 + t] = bt1[t];
        P[Pb2 + t] = b2[t]; P[Pg2 + t] = g2[t]; P[Pt2 + t] = bt2[t];
    }
    P[Pbw + tid] = bw[tid]; P[Pgw + tid] = gw[tid]; P[Ptw + tid] = btw[tid];
    if (tid < 64) P[Pb3 + tid] = b3[tid];
    if (tid < 32) {
        int e = e0 + tid;
        bsm[tid] = (e < E) ? (is64 ? (int)((const long long*)braw)[e]
                                   : ((const int*)braw)[e]) : 0;
    }
    __syncthreads();

    // winding MLP -> fp16 frag-packed A kb 16..23 (= x cols 256..383); 8 rows/warp
#pragma unroll 1
    for (int rr = 0; rr < 8; rr++) {
        int r = warp * 8 + rr, e = e0 + r;
        float w0 = 0.f, w1 = 0.f;
        if (e < E) { w0 = wind[(size_t)e * 2]; w1 = wind[(size_t)e * 2 + 1]; }
        float v[4], s = 0.f, q = 0.f;
#pragma unroll
        for (int j = 0; j < 4; j++) {
            int c = lane * 4 + j;
            float x = fmaf(w0, P[PWw + c], fmaf(w1, P[PWw + 128 + c], P[Pbw + c]));
            v[j] = x; s += x; q += x * x;
        }
#pragma unroll
        for (int o = 16; o; o >>= 1) {
            s += __shfl_xor_sync(~0u, s, o);
            q += __shfl_xor_sync(~0u, q, o);
        }
        float mu = s * (1.f / 128.f);
        float var = fmaf(-mu, mu, q * (1.f / 128.f));
        float rsd = rsqrtf(var + 1e-5f);
#pragma unroll
        for (int j = 0; j < 4; j++) {
            int c = lane * 4 + j;
            v[j] = fmaxf(fmaf((v[j] - mu) * rsd, P[Pgw + c], P[Ptw + c]), 0.f);
        }
        const int c0 = lane * 4;
        const int kb = 16 + (c0 >> 4), lc = c0 & 15;
        const int tg0 = (lc & 7) >> 1, hic = lc >> 3;
        const int mb = r >> 4, gidr = r & 7, hir = (r >> 3) & 1;
        const int w = a_word(mb, kb) + (gidr * 4 + tg0) * 4 + hir + 2 * hic;
        As[w]     = h2u(__floats2half2_rn(v[0], v[1]));
        As[w + 4] = h2u(__floats2half2_rn(v[2], v[3]));
    }

    // stage x: src|dest|ea|u[batch] -> fp16 frag-packed A kb 0..15
#pragma unroll 1
    for (int idx = tid; idx < ROWS * 16; idx += THREADS) {
        int r = idx >> 4, c4 = (idx & 15) * 4;
        int e = e0 + r;
        float4 vv[4];
        vv[0] = vv[1] = vv[2] = vv[3] = make_float4(0.f, 0.f, 0.f, 0.f);
        if (e < E) {
            size_t o = (size_t)e * 64 + c4;
            vv[0] = *(const float4*)(src + o);
            vv[1] = *(const float4*)(dst_ + o);
            vv[2] = *(const float4*)(ea + o);
        }
        vv[3] = *(const float4*)(u + (size_t)bsm[r] * 64 + c4);
        const int mb = r >> 4, gidr = r & 7, hir = (r >> 3) & 1;
        const int lc = c4 & 15, tg0 = (lc & 7) >> 1, hic = lc >> 3;
        const int reg = hir + 2 * hic;
#pragma unroll
        for (int s = 0; s < 4; s++) {
            int kb = s * 4 + (c4 >> 4);
            int w = a_word(mb, kb) + (gidr * 4 + tg0) * 4 + reg;
            As[w]     = h2u(__floats2half2_rn(vv[s].x, vv[s].y));
            As[w + 4] = h2u(__floats2half2_rn(vv[s].z, vv[s].w));
        }
    }
    __syncthreads();   // full 24-kb A published

    const int gg = warp;               // 0..3 — col group
    const int nb0 = gg * 8;

    float acc[2][8][4];
#pragma unroll
    for (int mt = 0; mt < 2; mt++)
#pragma unroll
        for (int nt = 0; nt < 8; nt++)
#pragma unroll
            for (int j = 0; j < 4; j++) acc[mt][nt][j] = 0.f;

    // GEMM1: full K=384 in one contiguous pass (24 kb)
    gemm_ldg<24, 2, 8>(g_wt, 2048, As, acc, 0, gg, lane);

    // fused bias+LN+ReLU -> h1 (internal sync covers A-read completion)
    epilogue_ln(As, SQ, acc, P + Pb1, P + Pg1, P + Pt1, nb0, lane);
    __syncthreads();

    // GEMM2
#pragma unroll
    for (int mt = 0; mt < 2; mt++)
#pragma unroll
        for (int nt = 0; nt < 8; nt++)
#pragma unroll
            for (int j = 0; j < 4; j++) acc[mt][nt][j] = 0.f;
    gemm_ldg<16, 2, 8>(g_wt + W2B, 2048, As, acc, 0, gg, lane);

    epilogue_ln(As, SQ, acc, P + Pb2, P + Pg2, P + Pt2, nb0, lane);
    __syncthreads();

    // GEMM3 (32x64): 4 warps, MT=2 x NT=2; warp gg owns nb pair gg*2
    {
        const uint32_t* W3p = g_wt + W3B;
        float acc3[2][2][4];
#pragma unroll
        for (int mt = 0; mt < 2; mt++)
#pragma unroll
            for (int nt = 0; nt < 2; nt++)
#pragma unroll
                for (int j = 0; j < 4; j++) acc3[mt][nt][j] = 0.f;

        gemm_ldg<16, 2, 2>(W3p, 512, As, acc3, 0, gg, lane);

        // epilogue: +b3, store fp32
        const int nb03 = gg * 2;
#pragma unroll
        for (int mt = 0; mt < 2; mt++)
#pragma unroll
            for (int nt = 0; nt < 2; nt++) {
                int r0 = mt * 16 + gid;
                int c0 = (nb03 + nt) * 8 + 2 * tig;
                int e = e0 + r0;
                if (e < E)
                    *(float2*)(out + (size_t)e * 64 + c0) =
                        make_float2(acc3[mt][nt][0] + P[Pb3 + c0],
                                    acc3[mt][nt][1] + P[Pb3 + c0 + 1]);
                e = e0 + r0 + 8;
                if (e < E)
                    *(float2*)(out + (size_t)e * 64 + c0) =
                        make_float2(acc3[mt][nt][2] + P[Pb3 + c0],
                                    acc3[mt][nt][3] + P[Pb3 + c0 + 1]);
            }
    }
}

extern "C" void kernel_launch(void* const* d_in, const int* in_sizes, int n_in,
                              void* d_out, int out_size)
{
    const float* src = (const float*)d_in[0];
    const float* dst_ = (const float*)d_in[1];
    const float* ea = (const float*)d_in[2];
    const float* u = (const float*)d_in[3];
    const void* batch = d_in[4];
    const float* wind = (const float*)d_in[5];
    const float* Ww = (const float*)d_in[6];
    const float* bw = (const float*)d_in[7];
    const float* gw = (const float*)d_in[8];
    const float* btw = (const float*)d_in[9];
    const float* W1 = (const float*)d_in[10];
    const float* b1 = (const float*)d_in[11];
    const float* g1 = (const float*)d_in[12];
    const float* bt1 = (const float*)d_in[13];
    const float* W2 = (const float*)d_in[14];
    const float* b2 = (const float*)d_in[15];
    const float* g2 = (const float*)d_in[16];
    const float* bt2 = (const float*)d_in[17];
    const float* W3 = (const float*)d_in[18];
    const float* b3 = (const float*)d_in[19];
    const int E = in_sizes[0] / 64;

    cudaFuncSetAttribute(fused_edge_kernel,
                         cudaFuncAttributeMaxDynamicSharedMemorySize, SMEM_BYTES);

    prep_weights<<<352, 256>>>(W1, W2, W3, (const int*)batch);

    fused_edge_kernel<<<(E + ROWS - 1) / ROWS, THREADS, SMEM_BYTES>>>(
        src, dst_, ea, u, batch, wind,
        bw, gw, btw, Ww,
        b1, g1, bt1, b2, g2, bt2, b3, (float*)d_out, E);
}